// round 4
// baseline (speedup 1.0000x reference)
#include <cuda_runtime.h>
#include <cuda_fp16.h>
#include <math.h>
#include <stdint.h>

#define H 2048
#define NOPS 8
#define NNODES 7

// ---------------- device state (scratch; no allocations allowed) ----------------
__device__ float g_c[2][H];
__device__ float g_h[2][2][H];       // [buffer][layer][H], ping-pong
__device__ float g_inputs[H];
__device__ float g_anchors[NNODES + 2][H];
__device__ float g_anchors_w1[NNODES + 2][H];
__device__ float g_hw[H];
__device__ float g_lp, g_ent;
__device__ int   g_arc[4 * NNODES];

// fp16 staged weights (converted from inputs once per replay)
__device__ __half g_wih_h[2 * 4 * H * H];   // 67 MB
__device__ __half g_whh_h[2 * 4 * H * H];   // 67 MB
__device__ __half g_emba_h[H * H];          // 8.4 MB
__device__ __half g_hida_h[H * H];          // 8.4 MB

// ---------------- helpers ----------------
__device__ __forceinline__ float warp_reduce(float v) {
#pragma unroll
    for (int o = 16; o > 0; o >>= 1) v += __shfl_down_sync(0xffffffffu, v, o);
    return v;
}

__device__ __forceinline__ float sigf(float x) { return 1.0f / (1.0f + expf(-x)); }

// dot of 8 fp16 weights (uint4) against 8 fp32 activations (two float4s)
__device__ __forceinline__ float dot8(uint4 q, float4 a0, float4 a1) {
    const __half2* hh = (const __half2*)&q;
    float2 f0 = __half22float2(hh[0]);
    float2 f1 = __half22float2(hh[1]);
    float2 f2 = __half22float2(hh[2]);
    float2 f3 = __half22float2(hh[3]);
    float acc = f0.x * a0.x + f0.y * a0.y;
    acc += f1.x * a0.z + f1.y * a0.w;
    acc += f2.x * a1.x + f2.y * a1.y;
    acc += f3.x * a1.z + f3.y * a1.w;
    return acc;
}

// ---------------- threefry2x32 (exact JAX semantics) ----------------
__device__ __forceinline__ void threefry2x32(uint32_t k0, uint32_t k1,
                                             uint32_t x0, uint32_t x1,
                                             uint32_t& o0, uint32_t& o1) {
    uint32_t ks0 = k0, ks1 = k1, ks2 = k0 ^ k1 ^ 0x1BD11BDAu;
    x0 += ks0; x1 += ks1;
#define TF_ROUND(r) { x0 += x1; x1 = (x1 << (r)) | (x1 >> (32 - (r))); x1 ^= x0; }
    TF_ROUND(13) TF_ROUND(15) TF_ROUND(26) TF_ROUND(6)
    x0 += ks1; x1 += ks2 + 1u;
    TF_ROUND(17) TF_ROUND(29) TF_ROUND(16) TF_ROUND(24)
    x0 += ks2; x1 += ks0 + 2u;
    TF_ROUND(13) TF_ROUND(15) TF_ROUND(26) TF_ROUND(6)
    x0 += ks0; x1 += ks1 + 3u;
    TF_ROUND(17) TF_ROUND(29) TF_ROUND(16) TF_ROUND(24)
    x0 += ks1; x1 += ks2 + 4u;
    TF_ROUND(13) TF_ROUND(15) TF_ROUND(26) TF_ROUND(6)
    x0 += ks2; x1 += ks0 + 5u;
#undef TF_ROUND
    o0 = x0; o1 = x1;
}

__device__ __forceinline__ float gumbel_from_bits(uint32_t b) {
    float f = __uint_as_float((b >> 9) | 0x3f800000u) - 1.0f;
    float u = f + 1.17549435e-38f;
    return -logf(-logf(u));
}

// Exact JAX sampling (partitionable threefry): bits[i] = o0 ^ o1,
// counter = (0, i); key = fold_in(key(42), t) = threefry([0,42],[0,t]).
__device__ void sample_common(float* l, int n, int t, int slot) {
    float m = -1e30f;
    for (int i = 0; i < n; i++) m = fmaxf(m, l[i]);
    float lpv[NOPS + 1];
    float se = 0.0f;
    for (int i = 0; i < n; i++) { lpv[i] = l[i] - m; se += expf(lpv[i]); }
    float lse = logf(se);
    float ent_term = 0.0f;
    for (int i = 0; i < n; i++) { lpv[i] -= lse; ent_term += lpv[i] * expf(lpv[i]); }

    uint32_t k0, k1;
    threefry2x32(0u, 42u, 0u, (uint32_t)t, k0, k1);

    float best = -1e30f; int bi = 0;
    for (int i = 0; i < n; i++) {
        uint32_t o0, o1;
        threefry2x32(k0, k1, 0u, (uint32_t)i, o0, o1);
        float z = l[i] + gumbel_from_bits(o0 ^ o1);
        if (z > best) { best = z; bi = i; }
    }
    g_lp += lpv[bi];
    g_ent -= ent_term;
    g_arc[slot] = bi;
}

// ---------------- fp32 -> fp16 conversion (runs once per replay) ----------------
// Each thread handles 4 uint4 outputs (8 float4 loads in flight) per iter.
__global__ void __launch_bounds__(256) convert_fp16_kernel(
    const float* __restrict__ src, __half* __restrict__ dst, int n32) {
    int i = blockIdx.x * blockDim.x + threadIdx.x;
    int stride = gridDim.x * blockDim.x;
    const float4* s4 = (const float4*)src;
    uint4* d4 = (uint4*)dst;
    for (; i < n32; i += stride) {
        float4 a[8];
#pragma unroll
        for (int p = 0; p < 8; p++) a[p] = s4[8 * i + p];
#pragma unroll
        for (int p = 0; p < 4; p++) {
            __half2 h0 = __floats2half2_rn(a[2 * p].x, a[2 * p].y);
            __half2 h1 = __floats2half2_rn(a[2 * p].z, a[2 * p].w);
            __half2 h2 = __floats2half2_rn(a[2 * p + 1].x, a[2 * p + 1].y);
            __half2 h3 = __floats2half2_rn(a[2 * p + 1].z, a[2 * p + 1].w);
            uint4 q;
            q.x = *reinterpret_cast<uint32_t*>(&h0);
            q.y = *reinterpret_cast<uint32_t*>(&h1);
            q.z = *reinterpret_cast<uint32_t*>(&h2);
            q.w = *reinterpret_cast<uint32_t*>(&h3);
            d4[4 * i + p] = q;
        }
    }
}

// ---------------- init ----------------
__global__ void init_kernel(const float* __restrict__ w_emb) {
    int i = blockIdx.x * blockDim.x + threadIdx.x;
    if (i < (NNODES + 2) * H) ((float*)g_anchors)[i] = 0.0f;
    if (i < 2 * H) ((float*)g_c)[i] = 0.0f;
    if (i < 4 * H) ((float*)g_h)[i] = 0.0f;
    if (i < H) g_inputs[i] = w_emb[NOPS * H + i];
    if (i == 0) { g_lp = 0.0f; g_ent = 0.0f; }
}

// ---------------- fused LSTM cell (fp16 weights, fp32 accumulate) ----------------
// One block per output element j. 4 warps, warp w = gate w (i,f,g,o).
// All 16 weight uint4 loads are front-batched into registers (MLP=16/warp);
// activations are staged in smem and read back as float4 (LDS.128).
__global__ void __launch_bounds__(128) lstm_cell_kernel(
    const __half* __restrict__ Wih, const __half* __restrict__ Whh,
    const float* __restrict__ bih, const float* __restrict__ bhh,
    int layer, int src, int cur) {
    int j = blockIdx.x;
    int tid = threadIdx.x, w = tid >> 5, lane = tid & 31;
    __shared__ float xs[H], hs[H];
    __shared__ float sred[4];

    const float* x  = (src == 0) ? g_inputs : g_h[cur ^ 1][0];
    const float* hp = g_h[cur][layer];
#pragma unroll
    for (int i = tid; i < H / 4; i += 128) {
        ((float4*)xs)[i] = ((const float4*)x)[i];
        ((float4*)hs)[i] = ((const float4*)hp)[i];
    }

    float bsum = bih[w * H + j] + bhh[w * H + j];
    float cprev = (tid == 0) ? g_c[layer][j] : 0.0f;

    const uint4* rA = (const uint4*)(Wih + ((size_t)w * H + j) * H);
    const uint4* rB = (const uint4*)(Whh + ((size_t)w * H + j) * H);
    uint4 qa[8], qb[8];
#pragma unroll
    for (int i = 0; i < 8; i++) qa[i] = rA[i * 32 + lane];
#pragma unroll
    for (int i = 0; i < 8; i++) qb[i] = rB[i * 32 + lane];
    __syncthreads();

    float acc = 0.0f;
#pragma unroll
    for (int i = 0; i < 8; i++) {
        const float4* xp = (const float4*)&xs[(i * 32 + lane) * 8];
        acc += dot8(qa[i], xp[0], xp[1]);
    }
#pragma unroll
    for (int i = 0; i < 8; i++) {
        const float4* hp4 = (const float4*)&hs[(i * 32 + lane) * 8];
        acc += dot8(qb[i], hp4[0], hp4[1]);
    }
    acc = warp_reduce(acc);
    if (lane == 0) sred[w] = acc + bsum;
    __syncthreads();
    if (tid == 0) {
        float c2 = sigf(sred[1]) * cprev + sigf(sred[0]) * tanhf(sred[2]);
        float h2 = sigf(sred[3]) * tanhf(c2);
        g_c[layer][j] = c2;
        g_h[cur ^ 1][layer][j] = h2;
    }
}

// ---------------- 2048x2048 fp16 matvec: out[r] = dot(M[r,:], h1) ----------------
// dst_sel: 0 -> g_hw, 1 -> g_anchors_w1[dst_idx].
// fin_k >= 0: also register anchor fin_k (copy h1 -> anchors, reset inputs).
__global__ void __launch_bounds__(256) matvec_kernel(
    const __half* __restrict__ M, int dst_sel, int dst_idx, int cur,
    int fin_k, const float* __restrict__ w_emb) {
    __shared__ float vs[H];
    int tid = threadIdx.x, w = tid >> 5, lane = tid & 31;
    const float* v = g_h[cur][1];
#pragma unroll
    for (int i = tid; i < H / 4; i += 256) ((float4*)vs)[i] = ((const float4*)v)[i];

    int r = blockIdx.x * 8 + w;
    const uint4* row = (const uint4*)(M + (size_t)r * H);
    uint4 q[8];
#pragma unroll
    for (int i = 0; i < 8; i++) q[i] = row[i * 32 + lane];
    __syncthreads();

    float acc = 0.0f;
#pragma unroll
    for (int i = 0; i < 8; i++) {
        const float4* vp = (const float4*)&vs[(i * 32 + lane) * 8];
        acc += dot8(q[i], vp[0], vp[1]);
    }
    acc = warp_reduce(acc);
    if (lane == 0) {
        if (dst_sel == 0) g_hw[r] = acc;
        else              g_anchors_w1[dst_idx][r] = acc;
    }
    if (fin_k >= 0 && tid < 8) {
        int rr = blockIdx.x * 8 + tid;
        g_anchors[fin_k][rr] = vs[rr];
        g_inputs[rr] = w_emb[NOPS * H + rr];
    }
}

// ---------------- node-predecessor sampling ----------------
__global__ void __launch_bounds__(256) sample_node_kernel(
    const float* __restrict__ v_attn, int n, int t, int slot) {
    __shared__ float logits[8];
    __shared__ int s_idx;
    int w = threadIdx.x >> 5, lane = threadIdx.x & 31;
    if (w < n) {
        const float4* aw = (const float4*)g_anchors_w1[w];
        const float4* hw = (const float4*)g_hw;
        const float4* va = (const float4*)v_attn;
        float acc = 0.0f;
#pragma unroll
        for (int i = lane; i < H / 4; i += 32) {
            float4 a = aw[i], b = hw[i], c = va[i];
            acc += c.x * tanhf(a.x + b.x) + c.y * tanhf(a.y + b.y)
                 + c.z * tanhf(a.z + b.z) + c.w * tanhf(a.w + b.w);
        }
        acc = warp_reduce(acc);
        if (lane == 0) logits[w] = acc;
    }
    __syncthreads();
    if (threadIdx.x == 0) {
        float l[8];
        for (int i = 0; i < n; i++) l[i] = 2.5f * tanhf(logits[i] / 5.0f);
        sample_common(l, n, t, slot);
        s_idx = g_arc[slot];
    }
    __syncthreads();
    const float* src = g_anchors[s_idx];
    for (int i = threadIdx.x; i < H; i += 256) g_inputs[i] = src[i];
}

// ---------------- op sampling ----------------
__global__ void __launch_bounds__(256) sample_op_kernel(
    const float* __restrict__ w_soft_w, const float* __restrict__ w_soft_b,
    const float* __restrict__ w_emb, int t, int slot, int cur) {
    __shared__ float logits[8];
    __shared__ int s_idx;
    int w = threadIdx.x >> 5, lane = threadIdx.x & 31;
    {
        const float4* row = (const float4*)(w_soft_w + (size_t)w * H);
        const float4* h1 = (const float4*)g_h[cur][1];
        float acc = 0.0f;
#pragma unroll
        for (int i = lane; i < H / 4; i += 32) {
            float4 a = row[i], b = h1[i];
            acc += a.x * b.x + a.y * b.y + a.z * b.z + a.w * b.w;
        }
        acc = warp_reduce(acc);
        if (lane == 0) logits[w] = acc + w_soft_b[w];
    }
    __syncthreads();
    if (threadIdx.x == 0) {
        float l[8];
        for (int i = 0; i < 8; i++) l[i] = tanhf(logits[i] / 5.0f);  // TANH_C/OP_TANH_RED = 1
        sample_common(l, 8, t, slot);
        s_idx = g_arc[slot];
    }
    __syncthreads();
    const float* src = w_emb + (size_t)s_idx * H;
    for (int i = threadIdx.x; i < H; i += 256) g_inputs[i] = src[i];
}

// ---------------- finalize: out = [arc(28), log_p, entropy] ----------------
__global__ void finalize_kernel(float* __restrict__ out) {
    int i = threadIdx.x;
    if (i < 28) out[i] = (float)g_arc[i];
    if (i == 28) out[28] = g_lp;
    if (i == 29) out[29] = g_ent;
}

// ---------------- host driver (graph-capturable: launches only) ----------------
extern "C" void kernel_launch(void* const* d_in, const int* in_sizes, int n_in,
                              void* d_out, int out_size) {
    const float* w_emb    = (const float*)d_in[0];
    const float* emb_attn = (const float*)d_in[1];
    const float* hid_attn = (const float*)d_in[2];
    const float* v_attn   = (const float*)d_in[3];
    const float* w_soft_w = (const float*)d_in[4];
    const float* w_soft_b = (const float*)d_in[5];
    const float* w_ih     = (const float*)d_in[6];
    const float* w_hh     = (const float*)d_in[7];
    const float* b_ih     = (const float*)d_in[8];
    const float* b_hh     = (const float*)d_in[9];
    float* out = (float*)d_out;

    __half* wih_h; cudaGetSymbolAddress((void**)&wih_h, g_wih_h);
    __half* whh_h; cudaGetSymbolAddress((void**)&whh_h, g_whh_h);
    __half* emba_h; cudaGetSymbolAddress((void**)&emba_h, g_emba_h);
    __half* hida_h; cudaGetSymbolAddress((void**)&hida_h, g_hida_h);

    convert_fp16_kernel<<<2048, 256>>>(w_ih, wih_h, 2 * 4 * H * H / 32);
    convert_fp16_kernel<<<2048, 256>>>(w_hh, whh_h, 2 * 4 * H * H / 32);
    convert_fp16_kernel<<<512, 256>>>(emb_attn, emba_h, H * H / 32);
    convert_fp16_kernel<<<512, 256>>>(hid_attn, hida_h, H * H / 32);

    init_kernel<<<72, 256>>>(w_emb);

    int cur = 0;
    auto step = [&]() {
        for (int l = 0; l < 2; l++) {
            lstm_cell_kernel<<<H, 128>>>(
                wih_h + (size_t)l * 4 * H * H,
                whh_h + (size_t)l * 4 * H * H,
                b_ih + (size_t)l * 4 * H,
                b_hh + (size_t)l * 4 * H,
                l, l, cur);
        }
        cur ^= 1;
    };

    // warm-up: two steps registering zero anchors + their attn projections
    for (int k = 0; k < 2; k++) {
        step();
        matvec_kernel<<<256, 256>>>(emba_h, 1, k, cur, -1, w_emb);
    }

    int t = 0;
    for (int nid = 0; nid < NNODES; nid++) {
        for (int j = 0; j < 2; j++) {
            step();
            matvec_kernel<<<256, 256>>>(hida_h, 0, 0, cur, -1, w_emb);
            sample_node_kernel<<<1, 256>>>(v_attn, nid + 2, t, 4 * nid + 2 * j);
            t++;
        }
        for (int j = 0; j < 2; j++) {
            step();
            sample_op_kernel<<<1, 256>>>(w_soft_w, w_soft_b, w_emb, t,
                                         4 * nid + 1 + 2 * j, cur);
            t++;
        }
        // final step: register new anchor (copy fused into matvec epilogue)
        step();
        matvec_kernel<<<256, 256>>>(emba_h, 1, nid + 2, cur, nid + 2, w_emb);
    }

    finalize_kernel<<<1, 32>>>(out);
}

// round 5
// speedup vs baseline: 1.3752x; 1.3752x over previous
#include <cuda_runtime.h>
#include <cuda_fp16.h>
#include <math.h>
#include <stdint.h>

#define H 2048
#define NOPS 8
#define NNODES 7
#define NB 128          // persistent blocks (<= 148 SMs -> co-resident wave 1)
#define NT 512          // threads per block (16 warps)
#define OPB 16          // outputs per block = H / NB

// ---------------- device state (no allocations allowed) ----------------
__device__ float g_c[2][H];
__device__ float g_hbuf[2][2][H];     // [parity][layer][H]
__device__ float g_inputs[H];
__device__ float g_anchors[NNODES + 2][H];
__device__ float g_anchors_w1[NNODES + 2][H];
__device__ float g_hw[H];
__device__ float g_lp, g_ent;
__device__ int   g_arc[4 * NNODES];

// fp16 staged weights (converted in-kernel each run)
__device__ __half g_wih_h[2 * 4 * H * H];
__device__ __half g_whh_h[2 * 4 * H * H];
__device__ __half g_emba_h[H * H];
__device__ __half g_hida_h[H * H];

// software grid barrier (sense-reversing)
__device__ unsigned g_bar_arrive;
__device__ volatile unsigned g_bar_gen;

__device__ __forceinline__ void grid_sync() {
    __threadfence();           // publish this thread's prior writes
    __syncthreads();
    if (threadIdx.x == 0) {
        unsigned gen = g_bar_gen;
        if (atomicAdd(&g_bar_arrive, 1u) == NB - 1) {
            g_bar_arrive = 0;
            __threadfence();
            g_bar_gen = gen + 1;
        } else {
            while (g_bar_gen == gen) __nanosleep(32);
            __threadfence();
        }
    }
    __syncthreads();
}

// ---------------- helpers ----------------
__device__ __forceinline__ float warp_reduce(float v) {
#pragma unroll
    for (int o = 16; o > 0; o >>= 1) v += __shfl_down_sync(0xffffffffu, v, o);
    return v;
}

__device__ __forceinline__ float sigf(float x) { return 1.0f / (1.0f + expf(-x)); }

// dot of 8 fp16 weights against 8 fp32 activations (E = elems 8m..8m+3, O = 8m+4..8m+7)
__device__ __forceinline__ float dot8(uint4 q, float4 e, float4 o) {
    const __half2* hh = (const __half2*)&q;
    float2 f0 = __half22float2(hh[0]);
    float2 f1 = __half22float2(hh[1]);
    float2 f2 = __half22float2(hh[2]);
    float2 f3 = __half22float2(hh[3]);
    float acc = f0.x * e.x + f0.y * e.y;
    acc += f1.x * e.z + f1.y * e.w;
    acc += f2.x * o.x + f2.y * o.y;
    acc += f3.x * o.z + f3.y * o.w;
    return acc;
}

// full 4KB row dot: 8 front-batched uint4 loads (MLP), conflict-free E/O LDS.128
__device__ __forceinline__ float dotrow(const uint4* __restrict__ row,
                                        const float4* __restrict__ E,
                                        const float4* __restrict__ O, int lane) {
    uint4 q[8];
#pragma unroll
    for (int i = 0; i < 8; i++) q[i] = __ldcg(row + i * 32 + lane);
    float acc = 0.0f;
#pragma unroll
    for (int i = 0; i < 8; i++) {
        int m = i * 32 + lane;
        acc += dot8(q[i], E[m], O[m]);
    }
    return acc;
}

// ---------------- threefry2x32 (exact JAX semantics) ----------------
__device__ __forceinline__ void threefry2x32(uint32_t k0, uint32_t k1,
                                             uint32_t x0, uint32_t x1,
                                             uint32_t& o0, uint32_t& o1) {
    uint32_t ks0 = k0, ks1 = k1, ks2 = k0 ^ k1 ^ 0x1BD11BDAu;
    x0 += ks0; x1 += ks1;
#define TF_ROUND(r) { x0 += x1; x1 = (x1 << (r)) | (x1 >> (32 - (r))); x1 ^= x0; }
    TF_ROUND(13) TF_ROUND(15) TF_ROUND(26) TF_ROUND(6)
    x0 += ks1; x1 += ks2 + 1u;
    TF_ROUND(17) TF_ROUND(29) TF_ROUND(16) TF_ROUND(24)
    x0 += ks2; x1 += ks0 + 2u;
    TF_ROUND(13) TF_ROUND(15) TF_ROUND(26) TF_ROUND(6)
    x0 += ks0; x1 += ks1 + 3u;
    TF_ROUND(17) TF_ROUND(29) TF_ROUND(16) TF_ROUND(24)
    x0 += ks1; x1 += ks2 + 4u;
    TF_ROUND(13) TF_ROUND(15) TF_ROUND(26) TF_ROUND(6)
    x0 += ks2; x1 += ks0 + 5u;
#undef TF_ROUND
    o0 = x0; o1 = x1;
}

__device__ __forceinline__ float gumbel_from_bits(uint32_t b) {
    float f = __uint_as_float((b >> 9) | 0x3f800000u) - 1.0f;
    float u = f + 1.17549435e-38f;
    return -logf(-logf(u));
}

// Warp-parallel exact-JAX sampling (partitionable threefry: bits[i]=o0^o1,
// counter=(0,i); key = fold_in(key(42),t)). lv = tanh-scaled logit per lane
// (lane < n valid; others -1e30). Returns sampled index on all lanes.
__device__ int sample_warp(float lv, int n, int t, int slot) {
    int lane = threadIdx.x & 31;
    const unsigned mask = 0xffffffffu;
    float m = lv;
#pragma unroll
    for (int o = 16; o; o >>= 1) m = fmaxf(m, __shfl_xor_sync(mask, m, o));
    float sh = lv - m;
    float e = (lane < n) ? expf(sh) : 0.0f;
    float se = e;
#pragma unroll
    for (int o = 16; o; o >>= 1) se += __shfl_xor_sync(mask, se, o);
    float lse = logf(se);
    float lpv = sh - lse;
    float ent = (lane < n) ? lpv * expf(lpv) : 0.0f;
#pragma unroll
    for (int o = 16; o; o >>= 1) ent += __shfl_xor_sync(mask, ent, o);

    uint32_t k0, k1;
    threefry2x32(0u, 42u, 0u, (uint32_t)t, k0, k1);
    float z = -1e30f;
    if (lane < n) {
        uint32_t o0, o1;
        threefry2x32(k0, k1, 0u, (uint32_t)lane, o0, o1);
        z = lv + gumbel_from_bits(o0 ^ o1);
    }
    float bz = z;
    int bi = (lane < n) ? lane : (1 << 30);
#pragma unroll
    for (int o = 16; o; o >>= 1) {
        float oz = __shfl_xor_sync(mask, bz, o);
        int oi = __shfl_xor_sync(mask, bi, o);
        if (oz > bz || (oz == bz && oi < bi)) { bz = oz; bi = oi; }
    }
    float lpsel = __shfl_sync(mask, lpv, bi);
    if (lane == 0) {
        g_lp += lpsel;
        g_ent -= ent;
        g_arc[slot] = bi;
    }
    return bi;
}

// ---------------- in-kernel fp32 -> fp16 conversion ----------------
__device__ void conv_arr(const float* __restrict__ src, __half* __restrict__ dst, int n8) {
    int i = blockIdx.x * NT + threadIdx.x;
    const int stride = NB * NT;
    const float4* s4 = (const float4*)src;
    uint4* d4 = (uint4*)dst;
#pragma unroll 4
    for (; i < n8; i += stride) {
        float4 a = s4[2 * i];
        float4 b = s4[2 * i + 1];
        __half2 h0 = __floats2half2_rn(a.x, a.y);
        __half2 h1 = __floats2half2_rn(a.z, a.w);
        __half2 h2 = __floats2half2_rn(b.x, b.y);
        __half2 h3 = __floats2half2_rn(b.z, b.w);
        uint4 q;
        q.x = *reinterpret_cast<uint32_t*>(&h0);
        q.y = *reinterpret_cast<uint32_t*>(&h1);
        q.z = *reinterpret_cast<uint32_t*>(&h2);
        q.w = *reinterpret_cast<uint32_t*>(&h3);
        d4[i] = q;
    }
}

// ---------------- LSTM layer phase (all blocks) ----------------
// Warp w handles output j = blk*16 + w entirely: 4 gates x (Wih + Whh) rows.
__device__ void lstm_layer_phase(const __half* __restrict__ Wih,
                                 const __half* __restrict__ Whh,
                                 const float* __restrict__ bihL,
                                 const float* __restrict__ bhhL,
                                 const float* __restrict__ x,
                                 const float* __restrict__ hold,
                                 float* __restrict__ cvec,
                                 float* __restrict__ hnew,
                                 float4* sEx, float4* sOx,
                                 float4* sEh, float4* sOh) {
    int tid = threadIdx.x, w = tid >> 5, lane = tid & 31;
    if (tid < 256) {
        const float4* x4 = (const float4*)x;
        sEx[tid] = __ldcg(x4 + 2 * tid);
        sOx[tid] = __ldcg(x4 + 2 * tid + 1);
    } else {
        int m = tid - 256;
        const float4* h4 = (const float4*)hold;
        sEh[m] = __ldcg(h4 + 2 * m);
        sOh[m] = __ldcg(h4 + 2 * m + 1);
    }
    __syncthreads();
    int j = blockIdx.x * OPB + w;
    float acc[4];
#pragma unroll
    for (int g = 0; g < 4; g++) {
        acc[g]  = dotrow((const uint4*)(Wih + ((size_t)g * H + j) * H), sEx, sOx, lane);
        acc[g] += dotrow((const uint4*)(Whh + ((size_t)g * H + j) * H), sEh, sOh, lane);
    }
#pragma unroll
    for (int g = 0; g < 4; g++) acc[g] = warp_reduce(acc[g]);
    if (lane == 0) {
        float gi = acc[0] + bihL[0 * H + j] + bhhL[0 * H + j];
        float gf = acc[1] + bihL[1 * H + j] + bhhL[1 * H + j];
        float gg = acc[2] + bihL[2 * H + j] + bhhL[2 * H + j];
        float go = acc[3] + bihL[3 * H + j] + bhhL[3 * H + j];
        float c2 = sigf(gf) * cvec[j] + sigf(gi) * tanhf(gg);
        cvec[j] = c2;
        hnew[j] = sigf(go) * tanhf(c2);
    }
}

// ---------------- matvec phase (all blocks): dst[r] = dot(M[r,:], h1) ----------------
__device__ void matvec_phase(const __half* __restrict__ M,
                             const float* __restrict__ h1,
                             float* __restrict__ dst,
                             int fin_k, const float* __restrict__ w_emb,
                             float4* sEh, float4* sOh) {
    int tid = threadIdx.x, w = tid >> 5, lane = tid & 31;
    if (tid < 256) {
        const float4* h4 = (const float4*)h1;
        sEh[tid] = __ldcg(h4 + 2 * tid);
        sOh[tid] = __ldcg(h4 + 2 * tid + 1);
    }
    __syncthreads();
    int r = blockIdx.x * OPB + w;
    float a = dotrow((const uint4*)(M + (size_t)r * H), sEh, sOh, lane);
    a = warp_reduce(a);
    if (lane == 0) dst[r] = a;
    if (fin_k >= 0 && tid < OPB) {
        int j = blockIdx.x * OPB + tid;
        g_anchors[fin_k][j] = h1[j];       // own block's h writes -> coherent
        g_inputs[j] = w_emb[NOPS * H + j];
    }
}

// ---------------- sampling phases (block 0 only) ----------------
__device__ void sample_node_phase(const float* __restrict__ v_attn,
                                  int n, int t, int slot,
                                  float* s_log, int* s_sel) {
    int tid = threadIdx.x, w = tid >> 5, lane = tid & 31;
    if (w < n) {
        const float4* aw = (const float4*)g_anchors_w1[w];
        const float4* hw4 = (const float4*)g_hw;
        const float4* va = (const float4*)v_attn;
        float acc = 0.0f;
        for (int i = lane; i < H / 4; i += 32) {
            float4 a = __ldcg(aw + i), b = __ldcg(hw4 + i), c = va[i];
            acc += c.x * tanhf(a.x + b.x) + c.y * tanhf(a.y + b.y)
                 + c.z * tanhf(a.z + b.z) + c.w * tanhf(a.w + b.w);
        }
        acc = warp_reduce(acc);
        if (lane == 0) s_log[w] = acc;
    }
    __syncthreads();
    if (w == 0) {
        float lv = (lane < n) ? 2.5f * tanhf(s_log[lane] / 5.0f) : -1e30f;
        int bi = sample_warp(lv, n, t, slot);
        if (lane == 0) *s_sel = bi;
    }
    __syncthreads();
    int s = *s_sel;
    const float4* src = (const float4*)g_anchors[s];
    float4* dst = (float4*)g_inputs;
    for (int i = tid; i < H / 4; i += NT) dst[i] = __ldcg(src + i);
}

__device__ void sample_op_phase(const float* __restrict__ w_soft_w,
                                const float* __restrict__ w_soft_b,
                                const float* __restrict__ w_emb,
                                const float* __restrict__ h1,
                                int t, int slot, float* s_log, int* s_sel) {
    int tid = threadIdx.x, w = tid >> 5, lane = tid & 31;
    if (w < NOPS) {
        const float4* row = (const float4*)(w_soft_w + (size_t)w * H);
        const float4* h4 = (const float4*)h1;
        float acc = 0.0f;
        for (int i = lane; i < H / 4; i += 32) {
            float4 a = row[i], b = __ldcg(h4 + i);
            acc += a.x * b.x + a.y * b.y + a.z * b.z + a.w * b.w;
        }
        acc = warp_reduce(acc);
        if (lane == 0) s_log[w] = acc + w_soft_b[w];
    }
    __syncthreads();
    if (w == 0) {
        float lv = (lane < NOPS) ? tanhf(s_log[lane] / 5.0f) : -1e30f;  // TANH_C/OP_TANH_RED = 1
        int bi = sample_warp(lv, NOPS, t, slot);
        if (lane == 0) *s_sel = bi;
    }
    __syncthreads();
    int s = *s_sel;
    const float4* src = (const float4*)(w_emb + (size_t)s * H);
    float4* dst = (float4*)g_inputs;
    for (int i = tid; i < H / 4; i += NT) dst[i] = src[i];
}

// ---------------- the persistent kernel ----------------
__global__ void __launch_bounds__(NT, 1) controller_kernel(
    const float* __restrict__ w_emb, const float* __restrict__ emb_attn,
    const float* __restrict__ hid_attn, const float* __restrict__ v_attn,
    const float* __restrict__ w_soft_w, const float* __restrict__ w_soft_b,
    const float* __restrict__ w_ih, const float* __restrict__ w_hh,
    const float* __restrict__ b_ih, const float* __restrict__ b_hh,
    float* __restrict__ out) {
    __shared__ float4 sEx[256], sOx[256], sEh[256], sOh[256];
    __shared__ float s_log[NOPS];
    __shared__ int s_sel;

    // phase 0: fp16 weight staging + state init
    conv_arr(w_ih, g_wih_h, 2 * 4 * H * H / 8);
    conv_arr(w_hh, g_whh_h, 2 * 4 * H * H / 8);
    conv_arr(emb_attn, g_emba_h, H * H / 8);
    conv_arr(hid_attn, g_hida_h, H * H / 8);
    {
        int gid = blockIdx.x * NT + threadIdx.x;
        if (gid < (NNODES + 2) * H) ((float*)g_anchors)[gid] = 0.0f;
        if (gid < 2 * H) ((float*)g_c)[gid] = 0.0f;
        if (gid < 2 * 2 * H) ((float*)g_hbuf)[gid] = 0.0f;
        if (gid < H) g_inputs[gid] = w_emb[NOPS * H + gid];
        if (gid == 0) { g_lp = 0.0f; g_ent = 0.0f; }
    }
    grid_sync();

    const __half* Wih0 = g_wih_h;
    const __half* Wih1 = g_wih_h + (size_t)4 * H * H;
    const __half* Whh0 = g_whh_h;
    const __half* Whh1 = g_whh_h + (size_t)4 * H * H;
    const float* bih0 = b_ih;            const float* bhh0 = b_hh;
    const float* bih1 = b_ih + 4 * H;    const float* bhh1 = b_hh + 4 * H;

    int cur = 0;
#define DO_STEP() do {                                                        \
    lstm_layer_phase(Wih0, Whh0, bih0, bhh0, g_inputs, g_hbuf[cur][0],        \
                     g_c[0], g_hbuf[cur ^ 1][0], sEx, sOx, sEh, sOh);         \
    grid_sync();                                                              \
    lstm_layer_phase(Wih1, Whh1, bih1, bhh1, g_hbuf[cur ^ 1][0],              \
                     g_hbuf[cur][1], g_c[1], g_hbuf[cur ^ 1][1],              \
                     sEx, sOx, sEh, sOh);                                     \
    grid_sync();                                                              \
    cur ^= 1;                                                                 \
} while (0)

    // warm-up: two steps registering zero anchors + attn projections
    for (int k = 0; k < 2; k++) {
        DO_STEP();
        matvec_phase(g_emba_h, g_hbuf[cur][1], g_anchors_w1[k], -1, w_emb, sEh, sOh);
        grid_sync();
    }

    int t = 0;
    for (int nid = 0; nid < NNODES; nid++) {
        for (int jj = 0; jj < 2; jj++) {
            DO_STEP();
            matvec_phase(g_hida_h, g_hbuf[cur][1], g_hw, -1, w_emb, sEh, sOh);
            grid_sync();
            if (blockIdx.x == 0)
                sample_node_phase(v_attn, nid + 2, t, 4 * nid + 2 * jj, s_log, &s_sel);
            grid_sync();
            t++;
        }
        for (int jj = 0; jj < 2; jj++) {
            DO_STEP();
            if (blockIdx.x == 0)
                sample_op_phase(w_soft_w, w_soft_b, w_emb, g_hbuf[cur][1],
                                t, 4 * nid + 1 + 2 * jj, s_log, &s_sel);
            grid_sync();
            t++;
        }
        // anchor registration step; the last node's anchor never affects outputs
        if (nid < NNODES - 1) {
            DO_STEP();
            matvec_phase(g_emba_h, g_hbuf[cur][1], g_anchors_w1[nid + 2],
                         nid + 2, w_emb, sEh, sOh);
            grid_sync();
        }
    }
#undef DO_STEP

    if (blockIdx.x == 0) {
        int i = threadIdx.x;
        if (i < 28) out[i] = (float)g_arc[i];
        if (i == 28) out[28] = g_lp;
        if (i == 29) out[29] = g_ent;
    }
}

// ---------------- host driver: ONE persistent kernel launch ----------------
extern "C" void kernel_launch(void* const* d_in, const int* in_sizes, int n_in,
                              void* d_out, int out_size) {
    const float* w_emb    = (const float*)d_in[0];
    const float* emb_attn = (const float*)d_in[1];
    const float* hid_attn = (const float*)d_in[2];
    const float* v_attn   = (const float*)d_in[3];
    const float* w_soft_w = (const float*)d_in[4];
    const float* w_soft_b = (const float*)d_in[5];
    const float* w_ih     = (const float*)d_in[6];
    const float* w_hh     = (const float*)d_in[7];
    const float* b_ih     = (const float*)d_in[8];
    const float* b_hh     = (const float*)d_in[9];

    controller_kernel<<<NB, NT>>>(w_emb, emb_attn, hid_attn, v_attn,
                                  w_soft_w, w_soft_b, w_ih, w_hh, b_ih, b_hh,
                                  (float*)d_out);
}

// round 6
// speedup vs baseline: 1.3777x; 1.0018x over previous
#include <cuda_runtime.h>
#include <cuda_fp16.h>
#include <math.h>
#include <stdint.h>

#define H 2048
#define NOPS 8
#define NNODES 7
#define NB 148          // persistent blocks; <= SM count (148 B300 / 152 GB300)
#define NT 448          // 14 warps per block
#define WPB 14          // warps (output rows) per block; NB*WPB = 2072 >= H

// ---------------- device state (no allocations allowed) ----------------
__device__ float g_c[2][H];
__device__ float g_h0[2][H];          // layer-0 h ping-pong
__device__ float g_h1[2][H];          // layer-1 h ping-pong
__device__ float g_anchors[NNODES + 2][H];     // [0],[1] stay zero
__device__ float g_anchors_w1[NNODES + 2][H];
__device__ float g_hw[H];

// fp16 staged weights
__device__ __half g_wih_h[2 * 4 * H * H];
__device__ __half g_whh_h[2 * 4 * H * H];
__device__ __half g_emba_h[H * H];
__device__ __half g_hida_h[H * H];

// software grid barrier (sense-reversing)
__device__ unsigned g_bar_arrive;
__device__ volatile unsigned g_bar_gen;

__device__ __forceinline__ void grid_sync() {
    __threadfence();
    __syncthreads();
    if (threadIdx.x == 0) {
        unsigned gen = g_bar_gen;
        if (atomicAdd(&g_bar_arrive, 1u) == NB - 1) {
            g_bar_arrive = 0;
            __threadfence();
            g_bar_gen = gen + 1;
        } else {
            while (g_bar_gen == gen) __nanosleep(32);
            __threadfence();
        }
    }
    __syncthreads();
}

// ---------------- helpers ----------------
__device__ __forceinline__ float warp_reduce(float v) {
#pragma unroll
    for (int o = 16; o > 0; o >>= 1) v += __shfl_down_sync(0xffffffffu, v, o);
    return v;
}

__device__ __forceinline__ float sigf(float x) { return 1.0f / (1.0f + expf(-x)); }

// dot of 8 fp16 weights against 8 fp32 activations (E = elems 8m..8m+3, O = 8m+4..8m+7)
__device__ __forceinline__ float dot8(uint4 q, float4 e, float4 o) {
    const __half2* hh = (const __half2*)&q;
    float2 f0 = __half22float2(hh[0]);
    float2 f1 = __half22float2(hh[1]);
    float2 f2 = __half22float2(hh[2]);
    float2 f3 = __half22float2(hh[3]);
    float acc = f0.x * e.x + f0.y * e.y;
    acc += f1.x * e.z + f1.y * e.w;
    acc += f2.x * o.x + f2.y * o.y;
    acc += f3.x * o.z + f3.y * o.w;
    return acc;
}

// ---------------- threefry2x32 (exact JAX semantics) ----------------
__device__ __forceinline__ void threefry2x32(uint32_t k0, uint32_t k1,
                                             uint32_t x0, uint32_t x1,
                                             uint32_t& o0, uint32_t& o1) {
    uint32_t ks0 = k0, ks1 = k1, ks2 = k0 ^ k1 ^ 0x1BD11BDAu;
    x0 += ks0; x1 += ks1;
#define TF_ROUND(r) { x0 += x1; x1 = (x1 << (r)) | (x1 >> (32 - (r))); x1 ^= x0; }
    TF_ROUND(13) TF_ROUND(15) TF_ROUND(26) TF_ROUND(6)
    x0 += ks1; x1 += ks2 + 1u;
    TF_ROUND(17) TF_ROUND(29) TF_ROUND(16) TF_ROUND(24)
    x0 += ks2; x1 += ks0 + 2u;
    TF_ROUND(13) TF_ROUND(15) TF_ROUND(26) TF_ROUND(6)
    x0 += ks0; x1 += ks1 + 3u;
    TF_ROUND(17) TF_ROUND(29) TF_ROUND(16) TF_ROUND(24)
    x0 += ks1; x1 += ks2 + 4u;
    TF_ROUND(13) TF_ROUND(15) TF_ROUND(26) TF_ROUND(6)
    x0 += ks2; x1 += ks0 + 5u;
#undef TF_ROUND
    o0 = x0; o1 = x1;
}

__device__ __forceinline__ float gumbel_from_bits(uint32_t b) {
    float f = __uint_as_float((b >> 9) | 0x3f800000u) - 1.0f;
    float u = f + 1.17549435e-38f;
    return -logf(-logf(u));
}

// Warp-parallel exact-JAX sampling (partitionable threefry: bits[i]=o0^o1,
// counter=(0,i); key = fold_in(key(42),t)). Executed redundantly by warp 0
// of EVERY block; stats/arc live in block-local smem.
__device__ int sample_warp(float lv, int n, int t, int slot,
                           float* s_stats, int* s_arc) {
    int lane = threadIdx.x & 31;
    const unsigned mask = 0xffffffffu;
    float m = lv;
#pragma unroll
    for (int o = 16; o; o >>= 1) m = fmaxf(m, __shfl_xor_sync(mask, m, o));
    float sh = lv - m;
    float e = (lane < n) ? expf(sh) : 0.0f;
    float se = e;
#pragma unroll
    for (int o = 16; o; o >>= 1) se += __shfl_xor_sync(mask, se, o);
    float lse = logf(se);
    float lpv = sh - lse;
    float ent = (lane < n) ? lpv * expf(lpv) : 0.0f;
#pragma unroll
    for (int o = 16; o; o >>= 1) ent += __shfl_xor_sync(mask, ent, o);

    uint32_t k0, k1;
    threefry2x32(0u, 42u, 0u, (uint32_t)t, k0, k1);
    float z = -1e30f;
    if (lane < n) {
        uint32_t o0, o1;
        threefry2x32(k0, k1, 0u, (uint32_t)lane, o0, o1);
        z = lv + gumbel_from_bits(o0 ^ o1);
    }
    float bz = z;
    int bi = (lane < n) ? lane : (1 << 30);
#pragma unroll
    for (int o = 16; o; o >>= 1) {
        float oz = __shfl_xor_sync(mask, bz, o);
        int oi = __shfl_xor_sync(mask, bi, o);
        if (oz > bz || (oz == bz && oi < bi)) { bz = oz; bi = oi; }
    }
    float lpsel = __shfl_sync(mask, lpv, bi);
    if (lane == 0) {
        s_stats[0] += lpsel;
        s_stats[1] -= ent;
        s_arc[slot] = bi;
    }
    return bi;
}

// ---------------- fp32 -> fp16 conversion (grid-strided, 4x ILP) ----------------
__device__ void conv_arr(const float* __restrict__ src, __half* __restrict__ dst, int n8) {
    int gid = blockIdx.x * NT + threadIdx.x;
    const int stride = NB * NT;
    const float4* s4 = (const float4*)src;
    uint4* d4 = (uint4*)dst;
    int i = gid;
    for (; i + 3 * stride < n8; i += 4 * stride) {
        float4 a[8];
#pragma unroll
        for (int k = 0; k < 4; k++) {
            a[2 * k]     = __ldg(s4 + 2 * (size_t)(i + k * stride));
            a[2 * k + 1] = __ldg(s4 + 2 * (size_t)(i + k * stride) + 1);
        }
#pragma unroll
        for (int k = 0; k < 4; k++) {
            __half2 h0 = __floats2half2_rn(a[2 * k].x, a[2 * k].y);
            __half2 h1 = __floats2half2_rn(a[2 * k].z, a[2 * k].w);
            __half2 h2 = __floats2half2_rn(a[2 * k + 1].x, a[2 * k + 1].y);
            __half2 h3 = __floats2half2_rn(a[2 * k + 1].z, a[2 * k + 1].w);
            uint4 q;
            q.x = *reinterpret_cast<uint32_t*>(&h0);
            q.y = *reinterpret_cast<uint32_t*>(&h1);
            q.z = *reinterpret_cast<uint32_t*>(&h2);
            q.w = *reinterpret_cast<uint32_t*>(&h3);
            d4[i + k * stride] = q;
        }
    }
    for (; i < n8; i += stride) {
        float4 a0 = __ldg(s4 + 2 * (size_t)i);
        float4 a1 = __ldg(s4 + 2 * (size_t)i + 1);
        __half2 h0 = __floats2half2_rn(a0.x, a0.y);
        __half2 h1 = __floats2half2_rn(a0.z, a0.w);
        __half2 h2 = __floats2half2_rn(a1.x, a1.y);
        __half2 h3 = __floats2half2_rn(a1.z, a1.w);
        uint4 q;
        q.x = *reinterpret_cast<uint32_t*>(&h0);
        q.y = *reinterpret_cast<uint32_t*>(&h1);
        q.z = *reinterpret_cast<uint32_t*>(&h2);
        q.w = *reinterpret_cast<uint32_t*>(&h3);
        d4[i] = q;
    }
}

// ---------------- LSTM layer phase ----------------
// Warp (global id gw) owns output gw: 4 gates x (Wih row + Whh row), with the
// 8 row-dots software-pipelined through two register buffers (loads of row
// r+1 issued before consuming row r -> memory stays busy).
__device__ void lstm_phase(const __half* __restrict__ Wih,
                           const __half* __restrict__ Whh,
                           const float* __restrict__ bihL,
                           const float* __restrict__ bhhL,
                           const float* __restrict__ xp, bool xz,
                           const float* __restrict__ hprev,
                           float* __restrict__ cvec,
                           float* __restrict__ hout,
                           float* __restrict__ anchor_dst,
                           float4* sEx, float4* sOx, float4* sEh, float4* sOh) {
    int tid = threadIdx.x, w = tid >> 5, lane = tid & 31;
    if (!xz) {
        const float4* x4 = (const float4*)xp;
        for (int i = tid; i < 256; i += NT) {
            sEx[i] = __ldcg(x4 + 2 * i);
            sOx[i] = __ldcg(x4 + 2 * i + 1);
        }
    }
    {
        const float4* h4 = (const float4*)hprev;
        for (int i = tid; i < 256; i += NT) {
            sEh[i] = __ldcg(h4 + 2 * i);
            sOh[i] = __ldcg(h4 + 2 * i + 1);
        }
    }
    __syncthreads();

    int gw = blockIdx.x * WPB + w;
    if (gw >= H) return;

#define ROWPTR(r) ((const uint4*)((r) < 4 ? Wih + ((size_t)(r) * H + gw) * H \
                                          : Whh + ((size_t)((r) - 4) * H + gw) * H))
    float acc[4] = {0.f, 0.f, 0.f, 0.f};
    uint4 bA[8], bB[8];
    int r0 = xz ? 4 : 0;                 // skip Wih rows entirely when x == 0
    {
        const uint4* rp = (r0 == 0) ? ROWPTR(0) : ROWPTR(4);
#pragma unroll
        for (int i = 0; i < 8; i++) bA[i] = __ldcg(rp + i * 32 + lane);
    }
    if (!xz) {
#pragma unroll
        for (int r = 0; r < 8; r++) {
            uint4* cur = (r & 1) ? bB : bA;
            uint4* nxt = (r & 1) ? bA : bB;
            if (r < 7) {
                const uint4* rp = ROWPTR(r + 1);
#pragma unroll
                for (int i = 0; i < 8; i++) nxt[i] = __ldcg(rp + i * 32 + lane);
            }
            const float4* E = (r < 4) ? sEx : sEh;
            const float4* O = (r < 4) ? sOx : sOh;
            float a = 0.0f;
#pragma unroll
            for (int i = 0; i < 8; i++) {
                int m = i * 32 + lane;
                a += dot8(cur[i], E[m], O[m]);
            }
            acc[r & 3] += a;
        }
    } else {
#pragma unroll
        for (int r = 4; r < 8; r++) {
            uint4* cur = (r & 1) ? bB : bA;
            uint4* nxt = (r & 1) ? bA : bB;
            if (r < 7) {
                const uint4* rp = ROWPTR(r + 1);
#pragma unroll
                for (int i = 0; i < 8; i++) nxt[i] = __ldcg(rp + i * 32 + lane);
            }
            float a = 0.0f;
#pragma unroll
            for (int i = 0; i < 8; i++) {
                int m = i * 32 + lane;
                a += dot8(cur[i], sEh[m], sOh[m]);
            }
            acc[r & 3] += a;
        }
    }
#undef ROWPTR
#pragma unroll
    for (int g = 0; g < 4; g++) acc[g] = warp_reduce(acc[g]);
    if (lane == 0) {
        float gi = acc[0] + bihL[0 * H + gw] + bhhL[0 * H + gw];
        float gf = acc[1] + bihL[1 * H + gw] + bhhL[1 * H + gw];
        float gg = acc[2] + bihL[2 * H + gw] + bhhL[2 * H + gw];
        float go = acc[3] + bihL[3 * H + gw] + bhhL[3 * H + gw];
        float c2 = sigf(gf) * cvec[gw] + sigf(gi) * tanhf(gg);
        float h2 = sigf(go) * tanhf(c2);
        cvec[gw] = c2;
        hout[gw] = h2;
        if (anchor_dst) anchor_dst[gw] = h2;
    }
}

// ---------------- matvec phase: dst[gw] = dot(M[gw,:], v) ----------------
__device__ void matvec_phase(const __half* __restrict__ M,
                             const float* __restrict__ v,
                             float* __restrict__ dst,
                             float4* sEh, float4* sOh) {
    int tid = threadIdx.x, w = tid >> 5, lane = tid & 31;
    const float4* h4 = (const float4*)v;
    for (int i = tid; i < 256; i += NT) {
        sEh[i] = __ldcg(h4 + 2 * i);
        sOh[i] = __ldcg(h4 + 2 * i + 1);
    }
    __syncthreads();
    int gw = blockIdx.x * WPB + w;
    if (gw >= H) return;
    const uint4* row = (const uint4*)(M + (size_t)gw * H);
    uint4 q[8];
#pragma unroll
    for (int i = 0; i < 8; i++) q[i] = __ldcg(row + i * 32 + lane);
    float acc = 0.0f;
#pragma unroll
    for (int i = 0; i < 8; i++) {
        int m = i * 32 + lane;
        acc += dot8(q[i], sEh[m], sOh[m]);
    }
    acc = warp_reduce(acc);
    if (lane == 0) dst[gw] = acc;
}

// ---------------- sampling (redundant across ALL blocks; smem-local state) ----------------
__device__ int node_sample(const float* __restrict__ v_attn, int n, int t, int slot,
                           float* s_log, int* s_sel, float* s_stats, int* s_arc) {
    int tid = threadIdx.x, w = tid >> 5, lane = tid & 31;
    if (w < n) {
        const float4* aw = (const float4*)g_anchors_w1[w];
        const float4* hw4 = (const float4*)g_hw;
        const float4* va = (const float4*)v_attn;
        float acc = 0.0f;
        for (int i = lane; i < H / 4; i += 32) {
            float4 a = __ldcg(aw + i), b = __ldcg(hw4 + i), c = __ldg(va + i);
            acc += c.x * tanhf(a.x + b.x) + c.y * tanhf(a.y + b.y)
                 + c.z * tanhf(a.z + b.z) + c.w * tanhf(a.w + b.w);
        }
        acc = warp_reduce(acc);
        if (lane == 0) s_log[w] = acc;
    }
    __syncthreads();
    if (w == 0) {
        float lv = (lane < n) ? 2.5f * tanhf(s_log[lane] / 5.0f) : -1e30f;
        int bi = sample_warp(lv, n, t, slot, s_stats, s_arc);
        if (lane == 0) *s_sel = bi;
    }
    __syncthreads();
    return *s_sel;
}

__device__ int op_sample(const float* __restrict__ w_soft_w,
                         const float* __restrict__ w_soft_b,
                         const float* __restrict__ h1,
                         int t, int slot,
                         float* s_log, int* s_sel, float* s_stats, int* s_arc) {
    int tid = threadIdx.x, w = tid >> 5, lane = tid & 31;
    if (w < NOPS) {
        const float4* row = (const float4*)(w_soft_w + (size_t)w * H);
        const float4* h4 = (const float4*)h1;
        float acc = 0.0f;
        for (int i = lane; i < H / 4; i += 32) {
            float4 a = __ldg(row + i), b = __ldcg(h4 + i);
            acc += a.x * b.x + a.y * b.y + a.z * b.z + a.w * b.w;
        }
        acc = warp_reduce(acc);
        if (lane == 0) s_log[w] = acc + __ldg(w_soft_b + w);
    }
    __syncthreads();
    if (w == 0) {
        float lv = (lane < NOPS) ? tanhf(s_log[lane] / 5.0f) : -1e30f;  // TANH_C/OP_TANH_RED = 1
        int bi = sample_warp(lv, NOPS, t, slot, s_stats, s_arc);
        if (lane == 0) *s_sel = bi;
    }
    __syncthreads();
    return *s_sel;
}

// ---------------- the persistent kernel ----------------
__global__ void __launch_bounds__(NT, 1) controller_kernel(
    const float* __restrict__ w_emb, const float* __restrict__ emb_attn,
    const float* __restrict__ hid_attn, const float* __restrict__ v_attn,
    const float* __restrict__ w_soft_w, const float* __restrict__ w_soft_b,
    const float* __restrict__ w_ih, const float* __restrict__ w_hh,
    const float* __restrict__ b_ih, const float* __restrict__ b_hh,
    float* __restrict__ out) {
    __shared__ float4 sEx[256], sOx[256], sEh[256], sOh[256];
    __shared__ float s_log[NOPS];
    __shared__ int s_sel;
    __shared__ float s_stats[2];          // [0]=log_p, [1]=entropy
    __shared__ int s_arc[4 * NNODES];

    // phase 0: fp16 staging + state init
    conv_arr(w_ih, g_wih_h, 2 * 4 * H * H / 8);
    conv_arr(w_hh, g_whh_h, 2 * 4 * H * H / 8);
    conv_arr(emb_attn, g_emba_h, H * H / 8);
    conv_arr(hid_attn, g_hida_h, H * H / 8);
    {
        int gid = blockIdx.x * NT + threadIdx.x;
        if (gid < (NNODES + 2) * H) ((float*)g_anchors)[gid] = 0.0f;
        if (gid < 2 * H) ((float*)g_c)[gid] = 0.0f;
        if (gid < 2 * H) ((float*)g_h0)[gid] = 0.0f;
        if (gid < 2 * H) ((float*)g_h1)[gid] = 0.0f;
        if (threadIdx.x == 0) { s_stats[0] = 0.0f; s_stats[1] = 0.0f; }
    }
    grid_sync();

    const __half* Wih0 = g_wih_h;
    const __half* Wih1 = g_wih_h + (size_t)4 * H * H;
    const __half* Whh0 = g_whh_h;
    const __half* Whh1 = g_whh_h + (size_t)4 * H * H;
    const float* bih0 = b_ih;            const float* bhh0 = b_hh;
    const float* bih1 = b_ih + 4 * H;    const float* bhh1 = b_hh + 4 * H;
    const float* gemb = w_emb + (size_t)NOPS * H;

    int cur = 0;
    const float* xp = gemb;
    bool xz = false;

#define STEP(ANCH) do {                                                       \
    lstm_phase(Wih0, Whh0, bih0, bhh0, xp, xz, g_h0[cur], g_c[0],             \
               g_h0[cur ^ 1], nullptr, sEx, sOx, sEh, sOh);                   \
    grid_sync();                                                              \
    lstm_phase(Wih1, Whh1, bih1, bhh1, g_h0[cur ^ 1], false, g_h1[cur],       \
               g_c[1], g_h1[cur ^ 1], (ANCH), sEx, sOx, sEh, sOh);            \
    grid_sync();                                                              \
    cur ^= 1;                                                                 \
} while (0)

    // warm-up: two steps registering zero anchors + attn projections
    for (int k = 0; k < 2; k++) {
        STEP(nullptr);
        matvec_phase(g_emba_h, g_h1[cur], g_anchors_w1[k], sEh, sOh);
        grid_sync();
    }

    int t = 0;
    for (int nid = 0; nid < NNODES; nid++) {
        // node-decision step 1 (x from previous flow: g-emb)
        STEP(nullptr);
        matvec_phase(g_hida_h, g_h1[cur], g_hw, sEh, sOh);
        grid_sync();
        int bi = node_sample(v_attn, nid + 2, t, 4 * nid, s_log, &s_sel, s_stats, s_arc);
        t++;
        xp = g_anchors[bi]; xz = (bi < 2);

        // node-decision step 2
        STEP(nullptr);
        matvec_phase(g_hida_h, g_h1[cur], g_hw, sEh, sOh);
        grid_sync();
        bi = node_sample(v_attn, nid + 2, t, 4 * nid + 2, s_log, &s_sel, s_stats, s_arc);
        t++;
        xp = g_anchors[bi]; xz = (bi < 2);

        // op step 1
        STEP(nullptr);
        int oi = op_sample(w_soft_w, w_soft_b, g_h1[cur], t, 4 * nid + 1,
                           s_log, &s_sel, s_stats, s_arc);
        t++;
        xp = w_emb + (size_t)oi * H; xz = false;

        // op step 2
        STEP(nullptr);
        oi = op_sample(w_soft_w, w_soft_b, g_h1[cur], t, 4 * nid + 3,
                       s_log, &s_sel, s_stats, s_arc);
        t++;
        xp = w_emb + (size_t)oi * H; xz = false;

        // anchor registration step (last node's anchor never affects outputs)
        if (nid < NNODES - 1) {
            STEP(g_anchors[nid + 2]);
            matvec_phase(g_emba_h, g_h1[cur], g_anchors_w1[nid + 2], sEh, sOh);
            grid_sync();
            xp = gemb; xz = false;
        }
    }
#undef STEP

    if (blockIdx.x == 0) {
        int i = threadIdx.x;
        if (i < 28) out[i] = (float)s_arc[i];
        if (i == 28) out[28] = s_stats[0];
        if (i == 29) out[29] = s_stats[1];
    }
}

// ---------------- host driver: ONE persistent kernel launch ----------------
extern "C" void kernel_launch(void* const* d_in, const int* in_sizes, int n_in,
                              void* d_out, int out_size) {
    const float* w_emb    = (const float*)d_in[0];
    const float* emb_attn = (const float*)d_in[1];
    const float* hid_attn = (const float*)d_in[2];
    const float* v_attn   = (const float*)d_in[3];
    const float* w_soft_w = (const float*)d_in[4];
    const float* w_soft_b = (const float*)d_in[5];
    const float* w_ih     = (const float*)d_in[6];
    const float* w_hh     = (const float*)d_in[7];
    const float* b_ih     = (const float*)d_in[8];
    const float* b_hh     = (const float*)d_in[9];

    controller_kernel<<<NB, NT>>>(w_emb, emb_attn, hid_attn, v_attn,
                                  w_soft_w, w_soft_b, w_ih, w_hh, b_ih, b_hh,
                                  (float*)d_out);
}

// round 7
// speedup vs baseline: 1.5476x; 1.1233x over previous
#include <cuda_runtime.h>
#include <cuda_fp16.h>
#include <math.h>
#include <stdint.h>

#define H 2048
#define NOPS 8
#define NNODES 7
#define NB 148          // persistent blocks; <= SM count (148 B300 / 152 GB300)
#define NT 448          // 14 warps per block
#define WPB 14          // warps (output rows) per block; NB*WPB = 2072 >= H

// ---------------- device state (no allocations allowed) ----------------
__device__ float g_c[2][H];
__device__ float g_h0[2][H];          // layer-0 h ping-pong
__device__ float g_h1[2][H];          // layer-1 h ping-pong
__device__ float g_anchors[NNODES + 2][H];     // [0],[1] stay zero
__device__ float g_anchors_w1[NNODES + 2][H];
__device__ float g_hw[H];
__device__ float g_pre[NOPS + 1][4][H];        // Wih0 @ w_emb[k], per gate
__device__ float g_bsum[2][4][H];              // b_ih + b_hh per layer/gate

// fp16 staged weights
__device__ __half g_wih_h[2 * 4 * H * H];
__device__ __half g_whh_h[2 * 4 * H * H];
__device__ __half g_emba_h[H * H];
__device__ __half g_hida_h[H * H];

// software grid barrier (sense-reversing)
__device__ unsigned g_bar_arrive;
__device__ volatile unsigned g_bar_gen;

__device__ __forceinline__ void grid_sync() {
    __threadfence();
    __syncthreads();
    if (threadIdx.x == 0) {
        unsigned gen = g_bar_gen;
        if (atomicAdd(&g_bar_arrive, 1u) == NB - 1) {
            g_bar_arrive = 0;
            __threadfence();
            g_bar_gen = gen + 1;
        } else {
            while (g_bar_gen == gen) __nanosleep(32);
            __threadfence();
        }
    }
    __syncthreads();
}

// ---------------- helpers ----------------
__device__ __forceinline__ float warp_reduce(float v) {
#pragma unroll
    for (int o = 16; o > 0; o >>= 1) v += __shfl_down_sync(0xffffffffu, v, o);
    return v;
}

__device__ __forceinline__ float sigf(float x) { return 1.0f / (1.0f + expf(-x)); }

// dot of 8 fp16 weights against 8 fp32 activations
__device__ __forceinline__ float dot8(uint4 q, float4 e, float4 o) {
    const __half2* hh = (const __half2*)&q;
    float2 f0 = __half22float2(hh[0]);
    float2 f1 = __half22float2(hh[1]);
    float2 f2 = __half22float2(hh[2]);
    float2 f3 = __half22float2(hh[3]);
    float acc = f0.x * e.x + f0.y * e.y;
    acc += f1.x * e.z + f1.y * e.w;
    acc += f2.x * o.x + f2.y * o.y;
    acc += f3.x * o.z + f3.y * o.w;
    return acc;
}

// full 4KB row dot vs smem E/O vectors (front-batch 8 LDG.128)
__device__ __forceinline__ float dotrow(const uint4* __restrict__ row,
                                        const float4* __restrict__ E,
                                        const float4* __restrict__ O, int lane) {
    uint4 q[8];
#pragma unroll
    for (int i = 0; i < 8; i++) q[i] = __ldcg(row + i * 32 + lane);
    float acc = 0.0f;
#pragma unroll
    for (int i = 0; i < 8; i++) {
        int m = i * 32 + lane;
        acc += dot8(q[i], E[m], O[m]);
    }
    return acc;
}

// ---------------- threefry2x32 (exact JAX semantics) ----------------
__device__ __forceinline__ void threefry2x32(uint32_t k0, uint32_t k1,
                                             uint32_t x0, uint32_t x1,
                                             uint32_t& o0, uint32_t& o1) {
    uint32_t ks0 = k0, ks1 = k1, ks2 = k0 ^ k1 ^ 0x1BD11BDAu;
    x0 += ks0; x1 += ks1;
#define TF_ROUND(r) { x0 += x1; x1 = (x1 << (r)) | (x1 >> (32 - (r))); x1 ^= x0; }
    TF_ROUND(13) TF_ROUND(15) TF_ROUND(26) TF_ROUND(6)
    x0 += ks1; x1 += ks2 + 1u;
    TF_ROUND(17) TF_ROUND(29) TF_ROUND(16) TF_ROUND(24)
    x0 += ks2; x1 += ks0 + 2u;
    TF_ROUND(13) TF_ROUND(15) TF_ROUND(26) TF_ROUND(6)
    x0 += ks0; x1 += ks1 + 3u;
    TF_ROUND(17) TF_ROUND(29) TF_ROUND(16) TF_ROUND(24)
    x0 += ks1; x1 += ks2 + 4u;
    TF_ROUND(13) TF_ROUND(15) TF_ROUND(26) TF_ROUND(6)
    x0 += ks2; x1 += ks0 + 5u;
#undef TF_ROUND
    o0 = x0; o1 = x1;
}

__device__ __forceinline__ float gumbel_from_bits(uint32_t b) {
    float f = __uint_as_float((b >> 9) | 0x3f800000u) - 1.0f;
    float u = f + 1.17549435e-38f;
    return -logf(-logf(u));
}

// Warp-parallel exact-JAX sampling (partitionable threefry). Redundant per block.
__device__ int sample_warp(float lv, int n, int t, int slot,
                           float* s_stats, int* s_arc) {
    int lane = threadIdx.x & 31;
    const unsigned mask = 0xffffffffu;
    float m = lv;
#pragma unroll
    for (int o = 16; o; o >>= 1) m = fmaxf(m, __shfl_xor_sync(mask, m, o));
    float sh = lv - m;
    float e = (lane < n) ? expf(sh) : 0.0f;
    float se = e;
#pragma unroll
    for (int o = 16; o; o >>= 1) se += __shfl_xor_sync(mask, se, o);
    float lse = logf(se);
    float lpv = sh - lse;
    float ent = (lane < n) ? lpv * expf(lpv) : 0.0f;
#pragma unroll
    for (int o = 16; o; o >>= 1) ent += __shfl_xor_sync(mask, ent, o);

    uint32_t k0, k1;
    threefry2x32(0u, 42u, 0u, (uint32_t)t, k0, k1);
    float z = -1e30f;
    if (lane < n) {
        uint32_t o0, o1;
        threefry2x32(k0, k1, 0u, (uint32_t)lane, o0, o1);
        z = lv + gumbel_from_bits(o0 ^ o1);
    }
    float bz = z;
    int bi = (lane < n) ? lane : (1 << 30);
#pragma unroll
    for (int o = 16; o; o >>= 1) {
        float oz = __shfl_xor_sync(mask, bz, o);
        int oi = __shfl_xor_sync(mask, bi, o);
        if (oz > bz || (oz == bz && oi < bi)) { bz = oz; bi = oi; }
    }
    float lpsel = __shfl_sync(mask, lpv, bi);
    if (lane == 0) {
        s_stats[0] += lpsel;
        s_stats[1] -= ent;
        s_arc[slot] = bi;
    }
    return bi;
}

// ---------------- fp32 -> fp16 conversion (grid-strided) ----------------
__device__ void conv_arr(const float* __restrict__ src, __half* __restrict__ dst, int n8) {
    int i = blockIdx.x * NT + threadIdx.x;
    const int stride = NB * NT;
    const float4* s4 = (const float4*)src;
    uint4* d4 = (uint4*)dst;
    for (; i < n8; i += stride) {
        float4 a0 = __ldg(s4 + 2 * (size_t)i);
        float4 a1 = __ldg(s4 + 2 * (size_t)i + 1);
        __half2 h0 = __floats2half2_rn(a0.x, a0.y);
        __half2 h1 = __floats2half2_rn(a0.z, a0.w);
        __half2 h2 = __floats2half2_rn(a1.x, a1.y);
        __half2 h3 = __floats2half2_rn(a1.z, a1.w);
        uint4 q;
        q.x = *reinterpret_cast<uint32_t*>(&h0);
        q.y = *reinterpret_cast<uint32_t*>(&h1);
        q.z = *reinterpret_cast<uint32_t*>(&h2);
        q.w = *reinterpret_cast<uint32_t*>(&h3);
        d4[i] = q;
    }
}

// ---------------- precompute g_pre[k][g][gw] = dot(Wih0[g*H+gw,:], w_emb[k,:]) ----
// One pass over fp16 Wih0; the 9 embedding vectors live in L1/L2 (73 KB).
__device__ void precompute_phase(const __half* __restrict__ Wih0,
                                 const float* __restrict__ w_emb) {
    int tid = threadIdx.x, w = tid >> 5, lane = tid & 31;
    int gw = blockIdx.x * WPB + w;
    if (gw >= H) return;
#pragma unroll
    for (int g = 0; g < 4; g++) {
        const uint4* rp = (const uint4*)(Wih0 + ((size_t)g * H + gw) * H);
        uint4 q[8];
#pragma unroll
        for (int i = 0; i < 8; i++) q[i] = __ldcg(rp + i * 32 + lane);
        float a9[NOPS + 1];
#pragma unroll
        for (int k = 0; k <= NOPS; k++) a9[k] = 0.0f;
#pragma unroll
        for (int i = 0; i < 8; i++) {
            int m = i * 32 + lane;
#pragma unroll
            for (int k = 0; k <= NOPS; k++) {
                const float4* wr = (const float4*)(w_emb + (size_t)k * H);
                a9[k] += dot8(q[i], __ldg(wr + 2 * m), __ldg(wr + 2 * m + 1));
            }
        }
#pragma unroll
        for (int k = 0; k <= NOPS; k++) {
            float r = warp_reduce(a9[k]);
            if (lane == 0) g_pre[k][g][gw] = r;
        }
    }
}

// ---------------- LSTM layer phase ----------------
// xk: -1 dense x (use xp), -2 zero x, >=0 embedding index (use g_pre, skip Wih).
__device__ void lstm_phase(const __half* __restrict__ Wih,
                           const __half* __restrict__ Whh,
                           const float* __restrict__ bsum,   // [4][H]
                           int xk, const float* __restrict__ xp,
                           const float* __restrict__ hprev,
                           float* __restrict__ cvec,
                           float* __restrict__ hout,
                           float* __restrict__ anchor_dst,
                           float4* sEx, float4* sOx, float4* sEh, float4* sOh) {
    int tid = threadIdx.x, w = tid >> 5, lane = tid & 31;
    if (xk == -1) {
        const float4* x4 = (const float4*)xp;
        for (int i = tid; i < 256; i += NT) {
            sEx[i] = __ldcg(x4 + 2 * i);
            sOx[i] = __ldcg(x4 + 2 * i + 1);
        }
    }
    {
        const float4* h4 = (const float4*)hprev;
        for (int i = tid; i < 256; i += NT) {
            sEh[i] = __ldcg(h4 + 2 * i);
            sOh[i] = __ldcg(h4 + 2 * i + 1);
        }
    }
    __syncthreads();

    int gw = blockIdx.x * WPB + w;
    if (gw >= H) return;

    float acc[4];
#pragma unroll
    for (int g = 0; g < 4; g++) acc[g] = 0.0f;
    if (xk == -1) {
#pragma unroll
        for (int g = 0; g < 4; g++)
            acc[g] += dotrow((const uint4*)(Wih + ((size_t)g * H + gw) * H), sEx, sOx, lane);
    }
#pragma unroll
    for (int g = 0; g < 4; g++)
        acc[g] += dotrow((const uint4*)(Whh + ((size_t)g * H + gw) * H), sEh, sOh, lane);
#pragma unroll
    for (int g = 0; g < 4; g++) acc[g] = warp_reduce(acc[g]);
    if (lane == 0) {
        float pb[4];
#pragma unroll
        for (int g = 0; g < 4; g++)
            pb[g] = (xk >= 0 ? __ldcg(&g_pre[xk][g][gw]) : 0.0f) + bsum[g * H + gw];
        float gi = acc[0] + pb[0];
        float gf = acc[1] + pb[1];
        float gg = acc[2] + pb[2];
        float go = acc[3] + pb[3];
        float c2 = sigf(gf) * cvec[gw] + sigf(gi) * tanhf(gg);
        float h2 = sigf(go) * tanhf(c2);
        cvec[gw] = c2;
        hout[gw] = h2;
        if (anchor_dst) anchor_dst[gw] = h2;
    }
}

// ---------------- matvec phase: dst[gw] = dot(M[gw,:], v) ----------------
__device__ void matvec_phase(const __half* __restrict__ M,
                             const float* __restrict__ v,
                             float* __restrict__ dst,
                             float4* sEh, float4* sOh) {
    int tid = threadIdx.x, w = tid >> 5, lane = tid & 31;
    const float4* h4 = (const float4*)v;
    for (int i = tid; i < 256; i += NT) {
        sEh[i] = __ldcg(h4 + 2 * i);
        sOh[i] = __ldcg(h4 + 2 * i + 1);
    }
    __syncthreads();
    int gw = blockIdx.x * WPB + w;
    if (gw >= H) return;
    float a = dotrow((const uint4*)(M + (size_t)gw * H), sEh, sOh, lane);
    a = warp_reduce(a);
    if (lane == 0) dst[gw] = a;
}

// ---------------- sampling (redundant across ALL blocks) ----------------
__device__ int node_sample(const float* __restrict__ v_attn, int n, int t, int slot,
                           float* s_log, int* s_sel, float* s_stats, int* s_arc) {
    int tid = threadIdx.x, w = tid >> 5, lane = tid & 31;
    if (w < n) {
        const float4* aw = (const float4*)g_anchors_w1[w];
        const float4* hw4 = (const float4*)g_hw;
        const float4* va = (const float4*)v_attn;
        float acc = 0.0f;
#pragma unroll 4
        for (int i = lane; i < H / 4; i += 32) {
            float4 a = __ldcg(aw + i), b = __ldcg(hw4 + i), c = __ldg(va + i);
            acc += c.x * tanhf(a.x + b.x) + c.y * tanhf(a.y + b.y)
                 + c.z * tanhf(a.z + b.z) + c.w * tanhf(a.w + b.w);
        }
        acc = warp_reduce(acc);
        if (lane == 0) s_log[w] = acc;
    }
    __syncthreads();
    if (w == 0) {
        float lv = (lane < n) ? 2.5f * tanhf(s_log[lane] / 5.0f) : -1e30f;
        int bi = sample_warp(lv, n, t, slot, s_stats, s_arc);
        if (lane == 0) *s_sel = bi;
    }
    __syncthreads();
    return *s_sel;
}

__device__ int op_sample(const float* __restrict__ w_soft_w,
                         const float* __restrict__ w_soft_b,
                         const float* __restrict__ h1,
                         int t, int slot,
                         float* s_log, int* s_sel, float* s_stats, int* s_arc) {
    int tid = threadIdx.x, w = tid >> 5, lane = tid & 31;
    if (w < NOPS) {
        const float4* row = (const float4*)(w_soft_w + (size_t)w * H);
        const float4* h4 = (const float4*)h1;
        float acc = 0.0f;
#pragma unroll 4
        for (int i = lane; i < H / 4; i += 32) {
            float4 a = __ldg(row + i), b = __ldcg(h4 + i);
            acc += a.x * b.x + a.y * b.y + a.z * b.z + a.w * b.w;
        }
        acc = warp_reduce(acc);
        if (lane == 0) s_log[w] = acc + __ldg(w_soft_b + w);
    }
    __syncthreads();
    if (w == 0) {
        float lv = (lane < NOPS) ? tanhf(s_log[lane] / 5.0f) : -1e30f;  // TANH_C/OP_TANH_RED = 1
        int bi = sample_warp(lv, NOPS, t, slot, s_stats, s_arc);
        if (lane == 0) *s_sel = bi;
    }
    __syncthreads();
    return *s_sel;
}

// ---------------- the persistent kernel ----------------
__global__ void __launch_bounds__(NT, 1) controller_kernel(
    const float* __restrict__ w_emb, const float* __restrict__ emb_attn,
    const float* __restrict__ hid_attn, const float* __restrict__ v_attn,
    const float* __restrict__ w_soft_w, const float* __restrict__ w_soft_b,
    const float* __restrict__ w_ih, const float* __restrict__ w_hh,
    const float* __restrict__ b_ih, const float* __restrict__ b_hh,
    float* __restrict__ out) {
    __shared__ float4 sEx[256], sOx[256], sEh[256], sOh[256];
    __shared__ float s_log[NOPS];
    __shared__ int s_sel;
    __shared__ float s_stats[2];          // [0]=log_p, [1]=entropy
    __shared__ int s_arc[4 * NNODES];

    // phase 0: fp16 staging + state init + combined biases
    conv_arr(w_ih, g_wih_h, 2 * 4 * H * H / 8);
    conv_arr(w_hh, g_whh_h, 2 * 4 * H * H / 8);
    conv_arr(emb_attn, g_emba_h, H * H / 8);
    conv_arr(hid_attn, g_hida_h, H * H / 8);
    {
        int gid = blockIdx.x * NT + threadIdx.x;
        if (gid < (NNODES + 2) * H) ((float*)g_anchors)[gid] = 0.0f;
        if (gid < 2 * H) ((float*)g_c)[gid] = 0.0f;
        if (gid < 2 * H) ((float*)g_h0)[gid] = 0.0f;
        if (gid < 2 * H) ((float*)g_h1)[gid] = 0.0f;
        if (gid < 2 * 4 * H) ((float*)g_bsum)[gid] = b_ih[gid] + b_hh[gid];
        if (threadIdx.x == 0) { s_stats[0] = 0.0f; s_stats[1] = 0.0f; }
    }
    grid_sync();

    // phase 1: Wih0 @ all-9-embeddings precompute (warp-local results)
    precompute_phase(g_wih_h, w_emb);
    grid_sync();

    const __half* Wih0 = g_wih_h;
    const __half* Wih1 = g_wih_h + (size_t)4 * H * H;
    const __half* Whh0 = g_whh_h;
    const __half* Whh1 = g_whh_h + (size_t)4 * H * H;
    const float* bs0 = &g_bsum[0][0][0];
    const float* bs1 = &g_bsum[1][0][0];

    int cur = 0;
    int xk = NOPS;                 // start input: g-embedding (w_emb row 8)
    const float* xp = nullptr;

#define STEP(ANCH) do {                                                       \
    lstm_phase(Wih0, Whh0, bs0, xk, xp, g_h0[cur], g_c[0],                    \
               g_h0[cur ^ 1], nullptr, sEx, sOx, sEh, sOh);                   \
    grid_sync();                                                              \
    lstm_phase(Wih1, Whh1, bs1, -1, g_h0[cur ^ 1], g_h1[cur],                 \
               g_c[1], g_h1[cur ^ 1], (ANCH), sEx, sOx, sEh, sOh);            \
    grid_sync();                                                              \
    cur ^= 1;                                                                 \
} while (0)

    // warm-up: two steps registering zero anchors + attn projections.
    // NOTE: no grid_sync after these matvecs — results consumed >=2 barriers later.
    for (int k = 0; k < 2; k++) {
        STEP(nullptr);
        matvec_phase(g_emba_h, g_h1[cur], g_anchors_w1[k], sEh, sOh);
        __syncthreads();
    }

    int t = 0;
    for (int nid = 0; nid < NNODES; nid++) {
        // node-decision step 1
        STEP(nullptr);
        matvec_phase(g_hida_h, g_h1[cur], g_hw, sEh, sOh);
        grid_sync();
        int bi = node_sample(v_attn, nid + 2, t, 4 * nid, s_log, &s_sel, s_stats, s_arc);
        t++;
        xk = (bi < 2) ? -2 : -1; xp = g_anchors[bi];

        // node-decision step 2
        STEP(nullptr);
        matvec_phase(g_hida_h, g_h1[cur], g_hw, sEh, sOh);
        grid_sync();
        bi = node_sample(v_attn, nid + 2, t, 4 * nid + 2, s_log, &s_sel, s_stats, s_arc);
        t++;
        xk = (bi < 2) ? -2 : -1; xp = g_anchors[bi];

        // op step 1
        STEP(nullptr);
        int oi = op_sample(w_soft_w, w_soft_b, g_h1[cur], t, 4 * nid + 1,
                           s_log, &s_sel, s_stats, s_arc);
        t++;
        xk = oi; xp = nullptr;

        // op step 2
        STEP(nullptr);
        oi = op_sample(w_soft_w, w_soft_b, g_h1[cur], t, 4 * nid + 3,
                       s_log, &s_sel, s_stats, s_arc);
        t++;
        xk = oi; xp = nullptr;

        // anchor registration step (last node's anchor never affects outputs)
        if (nid < NNODES - 1) {
            STEP(g_anchors[nid + 2]);
            matvec_phase(g_emba_h, g_h1[cur], g_anchors_w1[nid + 2], sEh, sOh);
            __syncthreads();           // block-local only; consumed >=2 barriers later
            xk = NOPS; xp = nullptr;
        }
    }
#undef STEP

    if (blockIdx.x == 0) {
        int i = threadIdx.x;
        if (i < 28) out[i] = (float)s_arc[i];
        if (i == 28) out[28] = s_stats[0];
        if (i == 29) out[29] = s_stats[1];
    }
}

// ---------------- host driver: ONE persistent kernel launch ----------------
extern "C" void kernel_launch(void* const* d_in, const int* in_sizes, int n_in,
                              void* d_out, int out_size) {
    const float* w_emb    = (const float*)d_in[0];
    const float* emb_attn = (const float*)d_in[1];
    const float* hid_attn = (const float*)d_in[2];
    const float* v_attn   = (const float*)d_in[3];
    const float* w_soft_w = (const float*)d_in[4];
    const float* w_soft_b = (const float*)d_in[5];
    const float* w_ih     = (const float*)d_in[6];
    const float* w_hh     = (const float*)d_in[7];
    const float* b_ih     = (const float*)d_in[8];
    const float* b_hh     = (const float*)d_in[9];

    controller_kernel<<<NB, NT>>>(w_emb, emb_attn, hid_attn, v_attn,
                                  w_soft_w, w_soft_b, w_ih, w_hh, b_ih, b_hh,
                                  (float*)d_out);
}